// round 2
// baseline (speedup 1.0000x reference)
#include <cuda_runtime.h>
#include <math.h>

#define B_    128
#define SEQ_  200
#define VOCAB_ 1400
#define D_    256
#define H_    256
#define NCLS_ 128
#define G4H   1024

// ---------------- scratch (static __device__, no allocations) ----------------
__device__ float g_embedded[B_ * SEQ_ * D_];          // 26 MB
__device__ float g_ux1[B_ * SEQ_ * G4H];              // 105 MB
__device__ float g_ux2[B_ * SEQ_ * G4H];              // 105 MB
__device__ float g_out1[B_ * SEQ_ * H_];              // 26 MB
__device__ float g_out2[B_ * SEQ_ * H_];              // 26 MB
__device__ float g_beta[B_ * SEQ_ * H_];              // 26 MB
__device__ float g_hbuf[2 * 2 * B_ * H_];             // [lstm][parity][b][h]
__device__ float g_cbuf[2 * 2 * B_ * H_];
__device__ float g_alpha[B_ * SEQ_];
__device__ float g_ctx[B_ * D_];

// ---------------- generic fp32 tiled GEMM ----------------
// C[m][n] = sum_k A[m][k] * Bm[.,.] (+ bias0[n] + bias1[n])
// BT=true : Bm is [N][K]  (row-major, K contiguous)   -> "NT"
// BT=false: Bm is [K][N]  (row-major, N contiguous)   -> "NN"
// Requires: M % 128 == 0, N % 64 == 0, K % 4 == 0.
#define GBM 128
#define GBN 64
#define GBK 16

template <bool BT>
__global__ void gemm_kernel(const float* __restrict__ A, const float* __restrict__ Bm,
                            float* __restrict__ C, int M, int N, int K,
                            const float* __restrict__ bias0, const float* __restrict__ bias1)
{
    __shared__ float As[GBK][GBM + 4];
    __shared__ float Bs[GBK][GBN + 4];

    const int tid   = threadIdx.x;       // 256 threads
    const int m_blk = blockIdx.y * GBM;
    const int n_blk = blockIdx.x * GBN;
    const int tx = tid & 15;             // n micro-tile
    const int ty = tid >> 4;             // m micro-tile
    const int m0 = ty * 8;
    const int n0 = tx * 4;

    float acc[8][4];
#pragma unroll
    for (int i = 0; i < 8; i++)
#pragma unroll
        for (int j = 0; j < 4; j++) acc[i][j] = 0.f;

    const int a_row = tid >> 2;          // 0..63
    const int a_c4  = (tid & 3) * 4;     // 0,4,8,12

    for (int k0 = 0; k0 < K; k0 += GBK) {
        // ---- load A tile (128 x 16), k-major into smem ----
#pragma unroll
        for (int r = 0; r < 2; r++) {
            int m = a_row + r * 64;
            float4 v = make_float4(0.f, 0.f, 0.f, 0.f);
            if (k0 + a_c4 < K)
                v = *reinterpret_cast<const float4*>(A + (size_t)(m_blk + m) * K + k0 + a_c4);
            As[a_c4 + 0][m] = v.x;
            As[a_c4 + 1][m] = v.y;
            As[a_c4 + 2][m] = v.z;
            As[a_c4 + 3][m] = v.w;
        }
        // ---- load B tile (16 x 64), k-major into smem ----
        if (BT) {
            int n  = tid >> 2;           // 0..63
            int c4 = (tid & 3) * 4;
            float4 v = make_float4(0.f, 0.f, 0.f, 0.f);
            if (k0 + c4 < K)
                v = *reinterpret_cast<const float4*>(Bm + (size_t)(n_blk + n) * K + k0 + c4);
            Bs[c4 + 0][n] = v.x;
            Bs[c4 + 1][n] = v.y;
            Bs[c4 + 2][n] = v.z;
            Bs[c4 + 3][n] = v.w;
        } else {
            int kk = tid >> 4;           // 0..15
            int nn = (tid & 15) * 4;     // 0..60
            float4 v = make_float4(0.f, 0.f, 0.f, 0.f);
            if (k0 + kk < K)
                v = *reinterpret_cast<const float4*>(Bm + (size_t)(k0 + kk) * N + n_blk + nn);
            *reinterpret_cast<float4*>(&Bs[kk][nn]) = v;
        }
        __syncthreads();

#pragma unroll
        for (int kk = 0; kk < GBK; kk++) {
            float4 a0 = *reinterpret_cast<const float4*>(&As[kk][m0]);
            float4 a1 = *reinterpret_cast<const float4*>(&As[kk][m0 + 4]);
            float4 b0 = *reinterpret_cast<const float4*>(&Bs[kk][n0]);
            float a[8] = {a0.x, a0.y, a0.z, a0.w, a1.x, a1.y, a1.z, a1.w};
            float b[4] = {b0.x, b0.y, b0.z, b0.w};
#pragma unroll
            for (int i = 0; i < 8; i++)
#pragma unroll
                for (int j = 0; j < 4; j++) acc[i][j] = fmaf(a[i], b[j], acc[i][j]);
        }
        __syncthreads();
    }

    float bv[4] = {0.f, 0.f, 0.f, 0.f};
    if (bias0) {
#pragma unroll
        for (int j = 0; j < 4; j++) bv[j] += bias0[n_blk + n0 + j];
    }
    if (bias1) {
#pragma unroll
        for (int j = 0; j < 4; j++) bv[j] += bias1[n_blk + n0 + j];
    }
#pragma unroll
    for (int i = 0; i < 8; i++) {
        float4 o;
        o.x = acc[i][0] + bv[0];
        o.y = acc[i][1] + bv[1];
        o.z = acc[i][2] + bv[2];
        o.w = acc[i][3] + bv[3];
        *reinterpret_cast<float4*>(C + (size_t)(m_blk + m0 + i) * N + n_blk + n0) = o;
    }
}

// ---------------- init recurrent state ----------------
__global__ void init_state_kernel(const float* __restrict__ h01, const float* __restrict__ c01,
                                  const float* __restrict__ h02, const float* __restrict__ c02)
{
    int i = blockIdx.x * blockDim.x + threadIdx.x;
    if (i >= B_ * H_) return;
    // [lstm][parity=0][b][h]
    g_hbuf[(0 * 2 + 0) * B_ * H_ + i] = h01[i];
    g_cbuf[(0 * 2 + 0) * B_ * H_ + i] = c01[i];
    g_hbuf[(1 * 2 + 0) * B_ * H_ + i] = h02[i];
    g_cbuf[(1 * 2 + 0) * B_ * H_ + i] = c02[i];
}

// ---------------- one LSTM time step (both LSTMs) ----------------
// grid: 256 blocks = lstm(2) x btile(8, 16 rows) x htile(16, 16 units); 256 threads.
#define TB 16
#define TH 16

__global__ void lstm_step_kernel(const float* __restrict__ Wall1, const float* __restrict__ Wd1,
                                 const float* __restrict__ Wdb1,
                                 const float* __restrict__ Wall2, const float* __restrict__ Wd2,
                                 const float* __restrict__ Wdb2,
                                 const float* __restrict__ tsp, int s, int par)
{
    const int bid   = blockIdx.x;
    const int lstm  = bid >> 7;
    const int btile = (bid >> 4) & 7;
    const int htile = bid & 15;
    const int b0 = btile * TB;
    const int j0 = htile * TH;

    const float* Wall = lstm ? Wall2 : Wall1;
    const float* Wd   = lstm ? Wd2   : Wd1;
    const float* Wdb  = lstm ? Wdb2  : Wdb1;
    const float* ux   = lstm ? g_ux2 : g_ux1;
    float*       outp = lstm ? g_out2 : g_out1;

    __shared__ float hs[TB][H_ + 4];
    __shared__ float cs[TB][H_ + 4];

    const int tid = threadIdx.x;
    const float* hsrc = g_hbuf + (size_t)(lstm * 2 + par) * B_ * H_;
    const float* csrc = g_cbuf + (size_t)(lstm * 2 + par) * B_ * H_;

    for (int idx = tid; idx < TB * H_ / 4; idx += 256) {
        int r = idx >> 6;            // H_/4 = 64 float4 per row
        int c = (idx & 63) * 4;
        *reinterpret_cast<float4*>(&hs[r][c]) =
            *reinterpret_cast<const float4*>(&hsrc[(size_t)(b0 + r) * H_ + c]);
        *reinterpret_cast<float4*>(&cs[r][c]) =
            *reinterpret_cast<const float4*>(&csrc[(size_t)(b0 + r) * H_ + c]);
    }
    __syncthreads();

    const int bi = tid & 15;
    const int ji = tid >> 4;
    const int b = b0 + bi;
    const int j = j0 + ji;

    const float* wf = Wall + (size_t)(0 * H_ + j) * H_;
    const float* wi = Wall + (size_t)(1 * H_ + j) * H_ + (size_t)(H_ * (H_ * 3));  // placeholder (fixed below)
    // NOTE: Wall is [4H][H]; rows: f=j, i=H+j, o=2H+j, c=3H+j
    wi = Wall + (size_t)(H_ + j) * H_;
    const float* wo = Wall + (size_t)(2 * H_ + j) * H_;
    const float* wc = Wall + (size_t)(3 * H_ + j) * H_;
    const float* wd = Wd + (size_t)j * H_;

    float af = 0.f, ai = 0.f, ao = 0.f, ac = 0.f, ad = 0.f;
#pragma unroll 4
    for (int k = 0; k < H_; k += 4) {
        float4 h4 = *reinterpret_cast<const float4*>(&hs[bi][k]);
        float4 c4 = *reinterpret_cast<const float4*>(&cs[bi][k]);
        float4 f4 = *reinterpret_cast<const float4*>(&wf[k]);
        float4 i4 = *reinterpret_cast<const float4*>(&wi[k]);
        float4 o4 = *reinterpret_cast<const float4*>(&wo[k]);
        float4 g4 = *reinterpret_cast<const float4*>(&wc[k]);
        float4 d4 = *reinterpret_cast<const float4*>(&wd[k]);
        af = fmaf(h4.x, f4.x, af); af = fmaf(h4.y, f4.y, af);
        af = fmaf(h4.z, f4.z, af); af = fmaf(h4.w, f4.w, af);
        ai = fmaf(h4.x, i4.x, ai); ai = fmaf(h4.y, i4.y, ai);
        ai = fmaf(h4.z, i4.z, ai); ai = fmaf(h4.w, i4.w, ai);
        ao = fmaf(h4.x, o4.x, ao); ao = fmaf(h4.y, o4.y, ao);
        ao = fmaf(h4.z, o4.z, ao); ao = fmaf(h4.w, o4.w, ao);
        ac = fmaf(h4.x, g4.x, ac); ac = fmaf(h4.y, g4.y, ac);
        ac = fmaf(h4.z, g4.z, ac); ac = fmaf(h4.w, g4.w, ac);
        ad = fmaf(c4.x, d4.x, ad); ad = fmaf(c4.y, d4.y, ad);
        ad = fmaf(c4.z, d4.z, ad); ad = fmaf(c4.w, d4.w, ad);
    }

    const size_t row = (size_t)b * SEQ_ + s;
    const float uxf = ux[row * G4H + 0 * H_ + j];
    const float uxi = ux[row * G4H + 1 * H_ + j];
    const float uxo = ux[row * G4H + 2 * H_ + j];
    const float uxc = ux[row * G4H + 3 * H_ + j];
    const float t   = tsp[row];

    const float cs1  = tanhf(ad + Wdb[j]);
    const float ccur = cs[bi][j];
    const float cadj = ccur - cs1 + cs1 * t;

    const float gf = 1.f / (1.f + expf(-(af + uxf)));
    const float gi = 1.f / (1.f + expf(-(ai + uxi)));
    const float go = 1.f / (1.f + expf(-(ao + uxo)));
    const float gc = 1.f / (1.f + expf(-(ac + uxc)));

    const float cnew = gf * cadj + gi * gc;
    const float hnew = go * tanhf(cnew);

    float* hdst = g_hbuf + (size_t)(lstm * 2 + (1 - par)) * B_ * H_;
    float* cdst = g_cbuf + (size_t)(lstm * 2 + (1 - par)) * B_ * H_;
    hdst[(size_t)b * H_ + j] = hnew;
    cdst[(size_t)b * H_ + j] = cnew;
    outp[row * H_ + j] = hnew;
}

// ---------------- attention: E = out1 . wa ; alpha = softmax_s(E) ----------------
__global__ void attn_softmax_kernel(const float* __restrict__ wa)
{
    const int b   = blockIdx.x;
    const int tid = threadIdx.x;       // 256
    const int lane = tid & 31;
    const int w    = tid >> 5;         // 8 warps
    __shared__ float Es[SEQ_];
    __shared__ float mx, sm;

    for (int s = w; s < SEQ_; s += 8) {
        const float* o = g_out1 + ((size_t)b * SEQ_ + s) * H_;
        float sum = 0.f;
        for (int h = lane; h < H_; h += 32) sum += o[h] * wa[h];
#pragma unroll
        for (int off = 16; off; off >>= 1) sum += __shfl_xor_sync(0xffffffffu, sum, off);
        if (lane == 0) Es[s] = sum;
    }
    __syncthreads();
    if (tid == 0) {
        float m = -1e30f;
        for (int s = 0; s < SEQ_; s++) m = fmaxf(m, Es[s]);
        mx = m;
    }
    __syncthreads();
    if (tid < SEQ_) Es[tid] = expf(Es[tid] - mx);
    __syncthreads();
    if (tid == 0) {
        float t = 0.f;
        for (int s = 0; s < SEQ_; s++) t += Es[s];
        sm = t;
    }
    __syncthreads();
    if (tid < SEQ_) g_alpha[(size_t)b * SEQ_ + tid] = Es[tid] / sm;
}

// ---------------- ctx[b][d] = sum_s emb[b,s,d] * tanh(beta[b,s,d]) * alpha[b,s] ----------------
__global__ void ctx_kernel()
{
    const int b = blockIdx.x;
    const int d = threadIdx.x;   // 256
    float acc = 0.f;
    for (int s = 0; s < SEQ_; s++) {
        size_t r = (size_t)b * SEQ_ + s;
        acc += g_embedded[r * D_ + d] * tanhf(g_beta[r * H_ + d]) * g_alpha[r];
    }
    g_ctx[(size_t)b * D_ + d] = acc;
}

// ---------------- out[b][n] = ctx[b] . Wout[n] ----------------
__global__ void out_kernel(const float* __restrict__ Wout, float* __restrict__ out)
{
    const int b = blockIdx.x;
    const int n = threadIdx.x;   // 128
    __shared__ float cx[D_];
    for (int d = threadIdx.x; d < D_; d += blockDim.x) cx[d] = g_ctx[(size_t)b * D_ + d];
    __syncthreads();
    float acc = 0.f;
    const float* wr = Wout + (size_t)n * H_;
#pragma unroll 8
    for (int d = 0; d < D_; d++) acc = fmaf(cx[d], wr[d], acc);
    out[(size_t)b * NCLS_ + n] = acc;
}

// ---------------- host launcher ----------------
extern "C" void kernel_launch(void* const* d_in, const int* in_sizes, int n_in,
                              void* d_out, int out_size)
{
    const float* inputs = (const float*)d_in[0];
    const float* tsp    = (const float*)d_in[1];
    const float* emb    = (const float*)d_in[2];
    const float* Wall1  = (const float*)d_in[3];
    const float* Wall1b = (const float*)d_in[4];
    const float* Uall1  = (const float*)d_in[5];
    const float* Uall1b = (const float*)d_in[6];
    const float* Wd1    = (const float*)d_in[7];
    const float* Wd1b   = (const float*)d_in[8];
    const float* Wall2  = (const float*)d_in[9];
    const float* Wall2b = (const float*)d_in[10];
    const float* Uall2  = (const float*)d_in[11];
    const float* Uall2b = (const float*)d_in[12];
    const float* Wd2    = (const float*)d_in[13];
    const float* Wd2b   = (const float*)d_in[14];
    const float* wa     = (const float*)d_in[15];
    const float* Wb     = (const float*)d_in[16];
    const float* Wout   = (const float*)d_in[17];
    const float* h01    = (const float*)d_in[18];
    const float* c01    = (const float*)d_in[19];
    const float* h02    = (const float*)d_in[20];
    const float* c02    = (const float*)d_in[21];
    float* out = (float*)d_out;

    void *p_emb, *p_ux1, *p_ux2, *p_out2, *p_beta;
    cudaGetSymbolAddress(&p_emb,  g_embedded);
    cudaGetSymbolAddress(&p_ux1,  g_ux1);
    cudaGetSymbolAddress(&p_ux2,  g_ux2);
    cudaGetSymbolAddress(&p_out2, g_out2);
    cudaGetSymbolAddress(&p_beta, g_beta);

    const int M = B_ * SEQ_;   // 25600

    // 1) embedded = inputs @ emb          (NN: B is [K][N])
    gemm_kernel<false><<<dim3(D_ / GBN, M / GBM), 256>>>(
        inputs, emb, (float*)p_emb, M, D_, VOCAB_, nullptr, nullptr);

    // 2) ux = embedded @ Uall^T + (Uall_b + Wall_b)   (NT)
    gemm_kernel<true><<<dim3(G4H / GBN, M / GBM), 256>>>(
        (const float*)p_emb, Uall1, (float*)p_ux1, M, G4H, D_, Uall1b, Wall1b);
    gemm_kernel<true><<<dim3(G4H / GBN, M / GBM), 256>>>(
        (const float*)p_emb, Uall2, (float*)p_ux2, M, G4H, D_, Uall2b, Wall2b);

    // 3) recurrent scan
    init_state_kernel<<<(B_ * H_ + 255) / 256, 256>>>(h01, c01, h02, c02);
    for (int s = 0; s < SEQ_; s++) {
        lstm_step_kernel<<<256, 256>>>(Wall1, Wd1, Wd1b, Wall2, Wd2, Wd2b, tsp, s, s & 1);
    }

    // 4) attention weights
    attn_softmax_kernel<<<B_, 256>>>(wa);

    // 5) beta = out2 @ Wb^T   (NT, raw; tanh fused into ctx)
    gemm_kernel<true><<<dim3(H_ / GBN, M / GBM), 256>>>(
        (const float*)p_out2, Wb, (float*)p_beta, M, H_, D_, nullptr, nullptr);

    // 6) context + output head
    ctx_kernel<<<B_, 256>>>();
    out_kernel<<<B_, 128>>>(Wout, out);
}

// round 3
// speedup vs baseline: 2.1377x; 2.1377x over previous
#include <cuda_runtime.h>
#include <math.h>

#define B_    128
#define SEQ_  200
#define VOCAB_ 1400
#define D_    256
#define H_    256
#define NCLS_ 128
#define G4H   1024

// ---------------- scratch (static __device__, no allocations) ----------------
__device__ float g_embedded[B_ * SEQ_ * D_];
__device__ float g_ux1[B_ * SEQ_ * G4H];
__device__ float g_ux2[B_ * SEQ_ * G4H];
__device__ float g_out1[B_ * SEQ_ * H_];
__device__ float g_out2[B_ * SEQ_ * H_];
__device__ float g_beta[B_ * SEQ_ * H_];
__device__ float g_hbuf[2 * 2 * B_ * H_];             // [lstm][parity][b][h]
__device__ float g_cbuf[2 * 2 * B_ * H_];
__device__ float g_alpha[B_ * SEQ_];
__device__ float g_ctx[B_ * D_];
__device__ unsigned g_cnt[16];
__device__ volatile unsigned g_gen[16];

// ---------------- packed fp32 helpers (sm_103a f32x2 pipe) ----------------
__device__ __forceinline__ void fma2(unsigned long long& d, unsigned long long a, unsigned long long b) {
    asm("fma.rn.f32x2 %0, %1, %2, %0;" : "+l"(d) : "l"(a), "l"(b));
}
__device__ __forceinline__ unsigned long long dup2(float v) {
    unsigned long long r;
    asm("mov.b64 %0, {%1, %1};" : "=l"(r) : "f"(v));
    return r;
}
__device__ __forceinline__ float2 unpack2(unsigned long long v) {
    float2 f;
    asm("mov.b64 {%0, %1}, %2;" : "=f"(f.x), "=f"(f.y) : "l"(v));
    return f;
}

// ---------------- generic fp32 tiled GEMM (f32x2 inner loop) ----------------
// C[m][n] = sum_k A[m][k] * Bm (+ bias0[n] + bias1[n])
// BT=true : Bm is [N][K]   BT=false: Bm is [K][N]
#define GBM 128
#define GBN 64
#define GBK 16

template <bool BT>
__global__ void gemm_kernel(const float* __restrict__ A, const float* __restrict__ Bm,
                            float* __restrict__ C, int M, int N, int K,
                            const float* __restrict__ bias0, const float* __restrict__ bias1)
{
    __shared__ float As[GBK][GBM + 4];
    __shared__ float Bs[GBK][GBN + 4];

    const int tid   = threadIdx.x;       // 256 threads
    const int m_blk = blockIdx.y * GBM;
    const int n_blk = blockIdx.x * GBN;
    const int tx = tid & 15;
    const int ty = tid >> 4;
    const int m0 = ty * 8;
    const int n0 = tx * 4;

    unsigned long long acc2[4][4];       // m-pairs x n
#pragma unroll
    for (int i = 0; i < 4; i++)
#pragma unroll
        for (int j = 0; j < 4; j++) acc2[i][j] = 0ULL;

    const int a_row = tid >> 2;
    const int a_c4  = (tid & 3) * 4;

    for (int k0 = 0; k0 < K; k0 += GBK) {
#pragma unroll
        for (int r = 0; r < 2; r++) {
            int m = a_row + r * 64;
            float4 v = make_float4(0.f, 0.f, 0.f, 0.f);
            if (k0 + a_c4 < K)
                v = *reinterpret_cast<const float4*>(A + (size_t)(m_blk + m) * K + k0 + a_c4);
            As[a_c4 + 0][m] = v.x;
            As[a_c4 + 1][m] = v.y;
            As[a_c4 + 2][m] = v.z;
            As[a_c4 + 3][m] = v.w;
        }
        if (BT) {
            int n  = tid >> 2;
            int c4 = (tid & 3) * 4;
            float4 v = make_float4(0.f, 0.f, 0.f, 0.f);
            if (k0 + c4 < K)
                v = *reinterpret_cast<const float4*>(Bm + (size_t)(n_blk + n) * K + k0 + c4);
            Bs[c4 + 0][n] = v.x;
            Bs[c4 + 1][n] = v.y;
            Bs[c4 + 2][n] = v.z;
            Bs[c4 + 3][n] = v.w;
        } else {
            int kk = tid >> 4;
            int nn = (tid & 15) * 4;
            float4 v = make_float4(0.f, 0.f, 0.f, 0.f);
            if (k0 + kk < K)
                v = *reinterpret_cast<const float4*>(Bm + (size_t)(k0 + kk) * N + n_blk + nn);
            *reinterpret_cast<float4*>(&Bs[kk][nn]) = v;
        }
        __syncthreads();

#pragma unroll
        for (int kk = 0; kk < GBK; kk++) {
            const ulonglong2* ap = reinterpret_cast<const ulonglong2*>(&As[kk][m0]);
            ulonglong2 aA = ap[0];
            ulonglong2 aB = ap[1];
            float4 b4 = *reinterpret_cast<const float4*>(&Bs[kk][n0]);
            unsigned long long bd[4] = {dup2(b4.x), dup2(b4.y), dup2(b4.z), dup2(b4.w)};
            unsigned long long P[4] = {aA.x, aA.y, aB.x, aB.y};
#pragma unroll
            for (int p = 0; p < 4; p++)
#pragma unroll
                for (int j = 0; j < 4; j++) fma2(acc2[p][j], P[p], bd[j]);
        }
        __syncthreads();
    }

    float bv[4] = {0.f, 0.f, 0.f, 0.f};
    if (bias0) {
#pragma unroll
        for (int j = 0; j < 4; j++) bv[j] += bias0[n_blk + n0 + j];
    }
    if (bias1) {
#pragma unroll
        for (int j = 0; j < 4; j++) bv[j] += bias1[n_blk + n0 + j];
    }
#pragma unroll
    for (int p = 0; p < 4; p++) {
        float2 r0 = unpack2(acc2[p][0]);
        float2 r1 = unpack2(acc2[p][1]);
        float2 r2 = unpack2(acc2[p][2]);
        float2 r3 = unpack2(acc2[p][3]);
        float4 oA = make_float4(r0.x + bv[0], r1.x + bv[1], r2.x + bv[2], r3.x + bv[3]);
        float4 oB = make_float4(r0.y + bv[0], r1.y + bv[1], r2.y + bv[2], r3.y + bv[3]);
        *reinterpret_cast<float4*>(C + (size_t)(m_blk + m0 + 2 * p) * N + n_blk + n0)     = oA;
        *reinterpret_cast<float4*>(C + (size_t)(m_blk + m0 + 2 * p + 1) * N + n_blk + n0) = oB;
    }
}

// ---------------- init recurrent state + barriers ----------------
__global__ void init_state_kernel(const float* __restrict__ h01, const float* __restrict__ c01,
                                  const float* __restrict__ h02, const float* __restrict__ c02)
{
    int i = blockIdx.x * blockDim.x + threadIdx.x;
    if (i < 16) { g_cnt[i] = 0; *((unsigned*)&g_gen[i]) = 0; }
    if (i >= B_ * H_) return;
    g_hbuf[(0 * 2 + 0) * B_ * H_ + i] = h01[i];
    g_cbuf[(0 * 2 + 0) * B_ * H_ + i] = c01[i];
    g_hbuf[(1 * 2 + 0) * B_ * H_ + i] = h02[i];
    g_cbuf[(1 * 2 + 0) * B_ * H_ + i] = c02[i];
}

// ---------------- persistent LSTM scan ----------------
// grid = 128 blocks: lstm(2) x btile(8, 16 batches) x jtile(8, 32 h-units)
// 1 block/SM guaranteed (197KB smem), 128 < 148 -> whole grid resident wave-1.
#define WJT 32
#define HS_STRIDE 260
#define SCAN_SMEM ((5 * WJT * 256 + 2 * 16 * HS_STRIDE) * 4)

__global__ __launch_bounds__(256) void lstm_scan_kernel(
    const float* __restrict__ Wall1, const float* __restrict__ Wd1, const float* __restrict__ Wdb1,
    const float* __restrict__ Wall2, const float* __restrict__ Wd2, const float* __restrict__ Wdb2,
    const float* __restrict__ tsp)
{
    extern __shared__ float sm[];
    float* wsm = sm;                           // [5][32][256]
    float* hsm = sm + 5 * WJT * 256;           // [16][260]
    float* csm = hsm + 16 * HS_STRIDE;         // [16][260]

    const int bid   = blockIdx.x;
    const int lstm  = bid >> 6;
    const int btile = (bid >> 3) & 7;
    const int jt    = bid & 7;
    const int b0 = btile * 16;
    const int j0 = jt * WJT;
    const int grp = lstm * 8 + btile;

    const float* Wall = lstm ? Wall2 : Wall1;
    const float* Wd   = lstm ? Wd2   : Wd1;
    const float* Wdb  = lstm ? Wdb2  : Wdb1;
    const float* ux   = lstm ? g_ux2 : g_ux1;
    float*       outp = lstm ? g_out2 : g_out1;

    const int tid = threadIdx.x;

    // ---- stage weights once ----
    for (int idx = tid; idx < 5 * WJT * 64; idx += 256) {
        int g   = idx >> 11;           // / (32*64)
        int rem = idx & 2047;
        int lj  = rem >> 6;
        int k4  = (rem & 63) << 2;
        const float* src = (g < 4) ? (Wall + (size_t)(g * H_ + j0 + lj) * H_ + k4)
                                   : (Wd   + (size_t)(j0 + lj) * H_ + k4);
        *reinterpret_cast<float4*>(&wsm[((g << 5) + lj) * 256 + k4]) =
            *reinterpret_cast<const float4*>(src);
    }

    const int bi = tid & 15;
    const int jj = tid >> 4;           // 0..15
    const int b  = b0 + bi;
    const int jA = j0 + jj;
    const int jB = jA + 16;
    const float wdbA = Wdb[jA];
    const float wdbB = Wdb[jB];

    const float* wA[5];
    const float* wB[5];
#pragma unroll
    for (int g = 0; g < 5; g++) {
        wA[g] = &wsm[((g << 5) + jj) * 256];
        wB[g] = &wsm[((g << 5) + jj + 16) * 256];
    }

    for (int s = 0; s < SEQ_; s++) {
        const int pr = s & 1;
        const float* hsrc = g_hbuf + (size_t)(lstm * 2 + pr) * B_ * H_;
        const float* csrc = g_cbuf + (size_t)(lstm * 2 + pr) * B_ * H_;
        for (int idx = tid; idx < 16 * 64; idx += 256) {
            int r  = idx >> 6;
            int c4 = (idx & 63) << 2;
            *reinterpret_cast<float4*>(&hsm[r * HS_STRIDE + c4]) =
                *reinterpret_cast<const float4*>(&hsrc[(size_t)(b0 + r) * H_ + c4]);
            *reinterpret_cast<float4*>(&csm[r * HS_STRIDE + c4]) =
                *reinterpret_cast<const float4*>(&csrc[(size_t)(b0 + r) * H_ + c4]);
        }
        __syncthreads();

        // prefetch per-thread step inputs (L2 latency hidden under the dots)
        const size_t row = (size_t)b * SEQ_ + s;
        const float t = tsp[row];
        const float* uxp = ux + row * G4H;
        float uxA[4], uxB[4];
#pragma unroll
        for (int g = 0; g < 4; g++) { uxA[g] = uxp[g * H_ + jA]; uxB[g] = uxp[g * H_ + jB]; }

        unsigned long long acc[10];
#pragma unroll
        for (int i = 0; i < 10; i++) acc[i] = 0ULL;
        const float* hrow = &hsm[bi * HS_STRIDE];
        const float* crow = &csm[bi * HS_STRIDE];

#pragma unroll 4
        for (int k = 0; k < H_; k += 4) {
            ulonglong2 h2 = *reinterpret_cast<const ulonglong2*>(&hrow[k]);
            ulonglong2 c2 = *reinterpret_cast<const ulonglong2*>(&crow[k]);
#pragma unroll
            for (int g = 0; g < 4; g++) {
                ulonglong2 w2 = *reinterpret_cast<const ulonglong2*>(&wA[g][k]);
                fma2(acc[g], h2.x, w2.x);
                fma2(acc[g], h2.y, w2.y);
                ulonglong2 v2 = *reinterpret_cast<const ulonglong2*>(&wB[g][k]);
                fma2(acc[5 + g], h2.x, v2.x);
                fma2(acc[5 + g], h2.y, v2.y);
            }
            ulonglong2 d2 = *reinterpret_cast<const ulonglong2*>(&wA[4][k]);
            fma2(acc[4], c2.x, d2.x);
            fma2(acc[4], c2.y, d2.y);
            ulonglong2 e2 = *reinterpret_cast<const ulonglong2*>(&wB[4][k]);
            fma2(acc[9], c2.x, e2.x);
            fma2(acc[9], c2.y, e2.y);
        }

        float* hdst = g_hbuf + (size_t)(lstm * 2 + (1 - pr)) * B_ * H_;
        float* cdst = g_cbuf + (size_t)(lstm * 2 + (1 - pr)) * B_ * H_;
#pragma unroll
        for (int half = 0; half < 2; half++) {
            const int base = half * 5;
            float2 vf = unpack2(acc[base + 0]);
            float2 vi = unpack2(acc[base + 1]);
            float2 vo = unpack2(acc[base + 2]);
            float2 vc = unpack2(acc[base + 3]);
            float2 vd = unpack2(acc[base + 4]);
            const float af = vf.x + vf.y;
            const float ai = vi.x + vi.y;
            const float ao = vo.x + vo.y;
            const float ag = vc.x + vc.y;
            const float ad = vd.x + vd.y;
            const int   j   = half ? jB : jA;
            const float wdb = half ? wdbB : wdbA;
            const float* uxv = half ? uxB : uxA;

            const float cs1  = tanhf(ad + wdb);
            const float ccur = crow[j];
            const float cadj = ccur - cs1 + cs1 * t;
            const float gf = 1.f / (1.f + expf(-(af + uxv[0])));
            const float gi = 1.f / (1.f + expf(-(ai + uxv[1])));
            const float go = 1.f / (1.f + expf(-(ao + uxv[2])));
            const float gc = 1.f / (1.f + expf(-(ag + uxv[3])));
            const float cnew = gf * cadj + gi * gc;
            const float hnew = go * tanhf(cnew);

            hdst[(size_t)b * H_ + j] = hnew;
            cdst[(size_t)b * H_ + j] = cnew;
            outp[row * H_ + j] = hnew;
        }

        // ---- per-group barrier (8 jtile blocks share a btile) ----
        __threadfence();
        __syncthreads();
        if (tid == 0) {
            unsigned arrived = atomicAdd(&g_cnt[grp], 1u);
            if (arrived == 7u) {
                g_cnt[grp] = 0;
                __threadfence();
                atomicAdd((unsigned*)&g_gen[grp], 1u);
            }
            while (g_gen[grp] < (unsigned)(s + 1)) { __nanosleep(32); }
        }
        __syncthreads();
        __threadfence();
    }
}

// ---------------- attention: E = out1 . wa ; alpha = softmax_s(E) ----------------
__global__ void attn_softmax_kernel(const float* __restrict__ wa)
{
    const int b    = blockIdx.x;
    const int tid  = threadIdx.x;
    const int lane = tid & 31;
    const int w    = tid >> 5;
    __shared__ float Es[SEQ_];
    __shared__ float mx, smv;

    for (int s = w; s < SEQ_; s += 8) {
        const float* o = g_out1 + ((size_t)b * SEQ_ + s) * H_;
        float sum = 0.f;
        for (int h = lane; h < H_; h += 32) sum += o[h] * wa[h];
#pragma unroll
        for (int off = 16; off; off >>= 1) sum += __shfl_xor_sync(0xffffffffu, sum, off);
        if (lane == 0) Es[s] = sum;
    }
    __syncthreads();
    if (tid == 0) {
        float m = -1e30f;
        for (int s = 0; s < SEQ_; s++) m = fmaxf(m, Es[s]);
        mx = m;
    }
    __syncthreads();
    if (tid < SEQ_) Es[tid] = expf(Es[tid] - mx);
    __syncthreads();
    if (tid == 0) {
        float t = 0.f;
        for (int s = 0; s < SEQ_; s++) t += Es[s];
        smv = t;
    }
    __syncthreads();
    if (tid < SEQ_) g_alpha[(size_t)b * SEQ_ + tid] = Es[tid] / smv;
}

// ---------------- ctx[b][d] = sum_s emb * tanh(beta) * alpha ----------------
__global__ void ctx_kernel()
{
    const int b = blockIdx.x;
    const int d = threadIdx.x;
    float acc = 0.f;
    for (int s = 0; s < SEQ_; s++) {
        size_t r = (size_t)b * SEQ_ + s;
        acc += g_embedded[r * D_ + d] * tanhf(g_beta[r * H_ + d]) * g_alpha[r];
    }
    g_ctx[(size_t)b * D_ + d] = acc;
}

// ---------------- out[b][n] = ctx[b] . Wout[n] ----------------
__global__ void out_kernel(const float* __restrict__ Wout, float* __restrict__ out)
{
    const int b = blockIdx.x;
    const int n = threadIdx.x;
    __shared__ float cx[D_];
    for (int d = threadIdx.x; d < D_; d += blockDim.x) cx[d] = g_ctx[(size_t)b * D_ + d];
    __syncthreads();
    float acc = 0.f;
    const float* wr = Wout + (size_t)n * H_;
#pragma unroll 8
    for (int d = 0; d < D_; d++) acc = fmaf(cx[d], wr[d], acc);
    out[(size_t)b * NCLS_ + n] = acc;
}

// ---------------- host launcher ----------------
extern "C" void kernel_launch(void* const* d_in, const int* in_sizes, int n_in,
                              void* d_out, int out_size)
{
    const float* inputs = (const float*)d_in[0];
    const float* tsp    = (const float*)d_in[1];
    const float* emb    = (const float*)d_in[2];
    const float* Wall1  = (const float*)d_in[3];
    const float* Wall1b = (const float*)d_in[4];
    const float* Uall1  = (const float*)d_in[5];
    const float* Uall1b = (const float*)d_in[6];
    const float* Wd1    = (const float*)d_in[7];
    const float* Wd1b   = (const float*)d_in[8];
    const float* Wall2  = (const float*)d_in[9];
    const float* Wall2b = (const float*)d_in[10];
    const float* Uall2  = (const float*)d_in[11];
    const float* Uall2b = (const float*)d_in[12];
    const float* Wd2    = (const float*)d_in[13];
    const float* Wd2b   = (const float*)d_in[14];
    const float* wa     = (const float*)d_in[15];
    const float* Wb     = (const float*)d_in[16];
    const float* Wout   = (const float*)d_in[17];
    const float* h01    = (const float*)d_in[18];
    const float* c01    = (const float*)d_in[19];
    const float* h02    = (const float*)d_in[20];
    const float* c02    = (const float*)d_in[21];
    float* out = (float*)d_out;

    void *p_emb, *p_ux1, *p_ux2, *p_out2, *p_beta;
    cudaGetSymbolAddress(&p_emb,  g_embedded);
    cudaGetSymbolAddress(&p_ux1,  g_ux1);
    cudaGetSymbolAddress(&p_ux2,  g_ux2);
    cudaGetSymbolAddress(&p_out2, g_out2);
    cudaGetSymbolAddress(&p_beta, g_beta);

    cudaFuncSetAttribute(lstm_scan_kernel,
                         cudaFuncAttributeMaxDynamicSharedMemorySize, SCAN_SMEM);

    const int M = B_ * SEQ_;   // 25600

    // 1) embedded = inputs @ emb
    gemm_kernel<false><<<dim3(D_ / GBN, M / GBM), 256>>>(
        inputs, emb, (float*)p_emb, M, D_, VOCAB_, nullptr, nullptr);

    // 2) ux = embedded @ Uall^T + (Uall_b + Wall_b)
    gemm_kernel<true><<<dim3(G4H / GBN, M / GBM), 256>>>(
        (const float*)p_emb, Uall1, (float*)p_ux1, M, G4H, D_, Uall1b, Wall1b);
    gemm_kernel<true><<<dim3(G4H / GBN, M / GBM), 256>>>(
        (const float*)p_emb, Uall2, (float*)p_ux2, M, G4H, D_, Uall2b, Wall2b);

    // 3) recurrent scan — single persistent kernel, all 200 steps
    init_state_kernel<<<(B_ * H_ + 255) / 256, 256>>>(h01, c01, h02, c02);
    lstm_scan_kernel<<<128, 256, SCAN_SMEM>>>(Wall1, Wd1, Wd1b, Wall2, Wd2, Wd2b, tsp);

    // 4) attention weights
    attn_softmax_kernel<<<B_, 256>>>(wa);

    // 5) beta = out2 @ Wb^T
    gemm_kernel<true><<<dim3(H_ / GBN, M / GBM), 256>>>(
        (const float*)p_out2, Wb, (float*)p_beta, M, H_, D_, nullptr, nullptr);

    // 6) context + output head
    ctx_kernel<<<B_, 256>>>();
    out_kernel<<<B_, 128>>>(Wout, out);
}